// round 6
// baseline (speedup 1.0000x reference)
#include <cuda_runtime.h>
#include <cuda_fp16.h>
#include <cstdint>

// ---------------- problem constants ----------------
#define BATCH   4096
#define IN_F    512
#define OUT_F   512
#define GRID_N  8
#define KSPLINE (IN_F * GRID_N)      // 4096
#define KDIM    (KSPLINE + IN_F)     // 4608

// ---------------- scratch (static device globals: allocation-free) ----------
__device__ __half F_buf[(size_t)BATCH * KDIM];   // ~36 MB fp16 features
__device__ __half W_buf[(size_t)OUT_F * KDIM];   // ~4.5 MB fp16 weights

// ---------------- helpers ----------------
__device__ __forceinline__ uint32_t smem_u32(const void* p) {
    uint32_t a;
    asm("{ .reg .u64 t; cvta.to.shared.u64 t, %1; cvt.u32.u64 %0, t; }"
        : "=r"(a) : "l"(p));
    return a;
}

#define SMEM_SWZ(off) ((off) ^ (((off) >> 3) & 0x70))

__device__ __forceinline__ void ldsm4(uint32_t& r0, uint32_t& r1,
                                      uint32_t& r2, uint32_t& r3,
                                      uint32_t addr) {
    asm volatile("ldmatrix.sync.aligned.m8n8.x4.shared.b16 {%0,%1,%2,%3}, [%4];"
                 : "=r"(r0), "=r"(r1), "=r"(r2), "=r"(r3) : "r"(addr));
}

__device__ __forceinline__ void mma16816(float* c, const uint32_t* a,
                                         uint32_t b0, uint32_t b1) {
    asm volatile(
        "mma.sync.aligned.m16n8k16.row.col.f32.f16.f16.f32 "
        "{%0,%1,%2,%3}, {%4,%5,%6,%7}, {%8,%9}, {%0,%1,%2,%3};"
        : "+f"(c[0]), "+f"(c[1]), "+f"(c[2]), "+f"(c[3])
        : "r"(a[0]), "r"(a[1]), "r"(a[2]), "r"(a[3]), "r"(b0), "r"(b1));
}

// ---------------- merged prep kernel ----------------
#define W_BLOCKS ((OUT_F * KDIM / 8) / 256)          // 1152
#define F_BLOCKS ((BATCH * IN_F) / 256)              // 8192

__global__ void prep_kernel(const float* __restrict__ x,
                            const float* __restrict__ sw,
                            const float* __restrict__ ba,
                            const float* __restrict__ gp) {
    if (blockIdx.x < W_BLOCKS) {
        int idx8 = blockIdx.x * 256 + threadIdx.x;     // 0 .. 294911
        int o   = idx8 / (KDIM / 8);                   // /576
        int kq  = idx8 - o * (KDIM / 8);
        int k   = kq * 8;
        float v[8];
        if (k < KSPLINE) {
            const float4* src = reinterpret_cast<const float4*>(
                sw + (size_t)o * KSPLINE + k);
            float4 f0 = src[0], f1 = src[1];
            v[0]=f0.x; v[1]=f0.y; v[2]=f0.z; v[3]=f0.w;
            v[4]=f1.x; v[5]=f1.y; v[6]=f1.z; v[7]=f1.w;
        } else {
            const float4* src = reinterpret_cast<const float4*>(
                ba + (size_t)o * IN_F + (k - KSPLINE));
            float4 f0 = src[0], f1 = src[1];
            v[0]=0.1f*f0.x; v[1]=0.1f*f0.y; v[2]=0.1f*f0.z; v[3]=0.1f*f0.w;
            v[4]=0.1f*f1.x; v[5]=0.1f*f1.y; v[6]=0.1f*f1.z; v[7]=0.1f*f1.w;
        }
        __half hv[8];
#pragma unroll
        for (int t = 0; t < 8; t++) hv[t] = __float2half(v[t]);
        *reinterpret_cast<uint4*>(&W_buf[(size_t)o * KDIM + k]) =
            *reinterpret_cast<const uint4*>(hv);
    } else {
        int idx = (blockIdx.x - W_BLOCKS) * 256 + threadIdx.x;
        int b = idx >> 9;            // /512
        int i = idx & 511;
        float xn = tanhf(x[idx]);

        __half hv[8];
#pragma unroll
        for (int g = 0; g < 8; g++) {
            float d = fabsf(xn - __ldg(&gp[g]));
            float vv;
            if (d < 0.5f) {
                vv = 1.0f + d * d * (6.0f * d - 6.0f);   // 1 - 6d^2 + 6d^3
            } else if (d < 1.0f) {
                float t = 1.0f - d;
                vv = 2.0f * t * t * t;
            } else {
                vv = 0.0f;
            }
            hv[g] = __float2half(vv);
        }
        *reinterpret_cast<uint4*>(&F_buf[(size_t)b * KDIM + (size_t)i * 8]) =
            *reinterpret_cast<const uint4*>(hv);
        F_buf[(size_t)b * KDIM + KSPLINE + i] = __float2half(xn);
    }
}

// ---------------- mma.sync GEMM: D = F @ W^T ----------------
// CTA tile 64 (M) x 128 (N) x 64 (K); 4 stages; 2 CTAs co-resident per SM.
#define TM 64
#define TN 128
#define KC 64
#define NITER (KDIM / KC)             // 72
#define STAGES 4
#define GEMM_THREADS 256
#define A_TILE_BYTES (TM * 128)       // 64 rows x 128B = 8 KB
#define B_TILE_BYTES (TN * 128)       // 128 rows x 128B = 16 KB
#define STAGE_BYTES  (A_TILE_BYTES + B_TILE_BYTES)   // 24 KB
#define SMEM_DYN_TOTAL (1024 + STAGES * STAGE_BYTES) // ~97 KB -> 2 CTAs/SM

__device__ __forceinline__ void load_stage(uint32_t tiles_base, int it,
                                           int tid, int m0, int n0) {
    uint32_t abase = tiles_base + (uint32_t)(it % STAGES) * STAGE_BYTES;
    uint32_t bbase = abase + A_TILE_BYTES;
    size_t k0 = (size_t)it * KC;
    const __half* Fs = F_buf + (size_t)m0 * KDIM + k0;
    const __half* Ws = W_buf + (size_t)n0 * KDIM + k0;
    // 1536 16B-chunks per stage: A = 512 (64 rows x 8), B = 1024 (128 rows x 8)
#pragma unroll
    for (int c = 0; c < 6; c++) {
        int chunk = tid + c * GEMM_THREADS;     // 0..1535
        int isB  = (chunk >= 512);
        int sub  = isB ? (chunk - 512) : chunk;
        int row  = sub >> 3;
        int q    = sub & 7;
        const __half* src = (isB ? Ws : Fs) + (size_t)row * KDIM + q * 8;
        uint32_t dst = (isB ? bbase : abase)
                     + SMEM_SWZ((uint32_t)(row * 128 + q * 16));
        asm volatile("cp.async.cg.shared.global [%0], [%1], 16;"
                     :: "r"(dst), "l"(src));
    }
    asm volatile("cp.async.commit_group;" ::: "memory");
}

__global__ void __launch_bounds__(GEMM_THREADS, 2)
kan_gemm_kernel(float* __restrict__ out) {
    extern __shared__ char smem[];
    uint32_t tiles_base = (smem_u32(smem) + 1023u) & ~1023u;

    int tid = threadIdx.x;
    int wid = tid >> 5;
    int lane = tid & 31;
    int m0 = (blockIdx.x >> 2) * TM;     // 64 M-tiles
    int n0 = (blockIdx.x & 3) * TN;      // 4 N-tiles

    // warp sub-tile: 2 (M) x 4 (N) warps, each 32x32
    int wm = (wid >> 2) * 32;
    int wn = (wid & 3) * 32;

    // ldmatrix lane mappings
    int a_row = lane & 15;
    int a_kh  = (lane >> 4) << 3;
    int b_nr  = (lane & 7) + ((lane >> 4) << 3);
    int b_kh  = ((lane >> 3) & 1) << 3;

    float acc[2][4][4];
#pragma unroll
    for (int i = 0; i < 2; i++)
#pragma unroll
        for (int j = 0; j < 4; j++)
#pragma unroll
            for (int t = 0; t < 4; t++) acc[i][j][t] = 0.0f;

    // preload STAGES-1 stages
#pragma unroll
    for (int s = 0; s < STAGES - 1; s++) load_stage(tiles_base, s, tid, m0, n0);

    for (int it = 0; it < NITER; it++) {
        // stage `it` must be complete; allow deeper prefetch to stay in flight
        if (it <= NITER - 3) {
            asm volatile("cp.async.wait_group 2;" ::: "memory");
        } else if (it == NITER - 2) {
            asm volatile("cp.async.wait_group 1;" ::: "memory");
        } else {
            asm volatile("cp.async.wait_group 0;" ::: "memory");
        }
        __syncthreads();

        if (it + STAGES - 1 < NITER)
            load_stage(tiles_base, it + STAGES - 1, tid, m0, n0);

        uint32_t Ab = tiles_base + (uint32_t)(it % STAGES) * STAGE_BYTES;
        uint32_t Bb = Ab + A_TILE_BYTES;

#pragma unroll
        for (int ks = 0; ks < 4; ks++) {
            int kk = ks * 16;
            uint32_t a[2][4];
#pragma unroll
            for (int mi = 0; mi < 2; mi++) {
                uint32_t addr = Ab + SMEM_SWZ(
                    (uint32_t)((wm + mi * 16 + a_row) * 128 + (kk + a_kh) * 2));
                ldsm4(a[mi][0], a[mi][1], a[mi][2], a[mi][3], addr);
            }
            uint32_t b[8];
#pragma unroll
            for (int j = 0; j < 2; j++) {
                uint32_t addr = Bb + SMEM_SWZ(
                    (uint32_t)((wn + j * 16 + b_nr) * 128 + (kk + b_kh) * 2));
                ldsm4(b[j * 4 + 0], b[j * 4 + 1], b[j * 4 + 2], b[j * 4 + 3], addr);
            }
#pragma unroll
            for (int mi = 0; mi < 2; mi++)
#pragma unroll
                for (int nb = 0; nb < 4; nb++)
                    mma16816(acc[mi][nb], a[mi], b[nb * 2], b[nb * 2 + 1]);
        }
    }

    // epilogue: register accumulators -> gmem (float2 stores)
    int g = lane >> 2;
    int q = lane & 3;
#pragma unroll
    for (int mi = 0; mi < 2; mi++) {
#pragma unroll
        for (int nb = 0; nb < 4; nb++) {
            int row = m0 + wm + mi * 16 + g;
            int col = n0 + wn + nb * 8 + q * 2;
            float2 v0 = make_float2(acc[mi][nb][0], acc[mi][nb][1]);
            float2 v1 = make_float2(acc[mi][nb][2], acc[mi][nb][3]);
            *reinterpret_cast<float2*>(&out[(size_t)row * OUT_F + col]) = v0;
            *reinterpret_cast<float2*>(&out[(size_t)(row + 8) * OUT_F + col]) = v1;
        }
    }
}

// ---------------- launch ----------------
extern "C" void kernel_launch(void* const* d_in, const int* in_sizes, int n_in,
                              void* d_out, int out_size) {
    const float* x  = (const float*)d_in[0];   // (4096, 512)
    const float* sw = (const float*)d_in[1];   // (512, 512, 8)
    const float* ba = (const float*)d_in[2];   // (512, 512)
    const float* gp = (const float*)d_in[3];   // (8,)
    float* out = (float*)d_out;                // (4096, 512)

    prep_kernel<<<W_BLOCKS + F_BLOCKS, 256>>>(x, sw, ba, gp);

    cudaFuncSetAttribute(kan_gemm_kernel,
                         cudaFuncAttributeMaxDynamicSharedMemorySize,
                         SMEM_DYN_TOTAL);
    kan_gemm_kernel<<<(BATCH / TM) * (OUT_F / TN), GEMM_THREADS,
                      SMEM_DYN_TOTAL>>>(out);
}

// round 7
// speedup vs baseline: 1.1472x; 1.1472x over previous
#include <cuda_runtime.h>
#include <cuda_fp16.h>
#include <cstdint>

// ---------------- problem constants ----------------
#define BATCH   4096
#define IN_F    512
#define OUT_F   512
#define GRID_N  8
#define KSPLINE (IN_F * GRID_N)      // 4096
#define KDIM    (KSPLINE + IN_F)     // 4608

// ---------------- scratch (static device globals: allocation-free) ----------
__device__ __half F_buf[(size_t)BATCH * KDIM];   // ~36 MB fp16 features
__device__ __half W_buf[(size_t)OUT_F * KDIM];   // ~4.5 MB fp16 weights

// ---------------- helpers ----------------
__device__ __forceinline__ uint32_t smem_u32(const void* p) {
    uint32_t a;
    asm("{ .reg .u64 t; cvta.to.shared.u64 t, %1; cvt.u32.u64 %0, t; }"
        : "=r"(a) : "l"(p));
    return a;
}

#define SMEM_SWZ(off) ((off) ^ (((off) >> 3) & 0x70))

__device__ __forceinline__ void ldsm4(uint32_t& r0, uint32_t& r1,
                                      uint32_t& r2, uint32_t& r3,
                                      uint32_t addr) {
    asm volatile("ldmatrix.sync.aligned.m8n8.x4.shared.b16 {%0,%1,%2,%3}, [%4];"
                 : "=r"(r0), "=r"(r1), "=r"(r2), "=r"(r3) : "r"(addr));
}

__device__ __forceinline__ void mma16816(float* c, const uint32_t* a,
                                         uint32_t b0, uint32_t b1) {
    asm volatile(
        "mma.sync.aligned.m16n8k16.row.col.f32.f16.f16.f32 "
        "{%0,%1,%2,%3}, {%4,%5,%6,%7}, {%8,%9}, {%0,%1,%2,%3};"
        : "+f"(c[0]), "+f"(c[1]), "+f"(c[2]), "+f"(c[3])
        : "r"(a[0]), "r"(a[1]), "r"(a[2]), "r"(a[3]), "r"(b0), "r"(b1));
}

// ---------------- merged prep kernel ----------------
#define W_BLOCKS ((OUT_F * KDIM / 8) / 256)          // 1152
#define F_BLOCKS ((BATCH * IN_F) / 256)              // 8192

__global__ void prep_kernel(const float* __restrict__ x,
                            const float* __restrict__ sw,
                            const float* __restrict__ ba,
                            const float* __restrict__ gp) {
    if (blockIdx.x < W_BLOCKS) {
        int idx8 = blockIdx.x * 256 + threadIdx.x;     // 0 .. 294911
        int o   = idx8 / (KDIM / 8);                   // /576
        int kq  = idx8 - o * (KDIM / 8);
        int k   = kq * 8;
        float v[8];
        if (k < KSPLINE) {
            const float4* src = reinterpret_cast<const float4*>(
                sw + (size_t)o * KSPLINE + k);
            float4 f0 = src[0], f1 = src[1];
            v[0]=f0.x; v[1]=f0.y; v[2]=f0.z; v[3]=f0.w;
            v[4]=f1.x; v[5]=f1.y; v[6]=f1.z; v[7]=f1.w;
        } else {
            const float4* src = reinterpret_cast<const float4*>(
                ba + (size_t)o * IN_F + (k - KSPLINE));
            float4 f0 = src[0], f1 = src[1];
            v[0]=0.1f*f0.x; v[1]=0.1f*f0.y; v[2]=0.1f*f0.z; v[3]=0.1f*f0.w;
            v[4]=0.1f*f1.x; v[5]=0.1f*f1.y; v[6]=0.1f*f1.z; v[7]=0.1f*f1.w;
        }
        __half hv[8];
#pragma unroll
        for (int t = 0; t < 8; t++) hv[t] = __float2half(v[t]);
        *reinterpret_cast<uint4*>(&W_buf[(size_t)o * KDIM + k]) =
            *reinterpret_cast<const uint4*>(hv);
    } else {
        int idx = (blockIdx.x - W_BLOCKS) * 256 + threadIdx.x;
        int b = idx >> 9;            // /512
        int i = idx & 511;
        float xn = tanhf(x[idx]);

        __half hv[8];
#pragma unroll
        for (int g = 0; g < 8; g++) {
            float d = fabsf(xn - __ldg(&gp[g]));
            float vv;
            if (d < 0.5f) {
                vv = 1.0f + d * d * (6.0f * d - 6.0f);   // 1 - 6d^2 + 6d^3
            } else if (d < 1.0f) {
                float t = 1.0f - d;
                vv = 2.0f * t * t * t;
            } else {
                vv = 0.0f;
            }
            hv[g] = __float2half(vv);
        }
        *reinterpret_cast<uint4*>(&F_buf[(size_t)b * KDIM + (size_t)i * 8]) =
            *reinterpret_cast<const uint4*>(hv);
        F_buf[(size_t)b * KDIM + KSPLINE + i] = __float2half(xn);
    }
}

// ---------------- mma.sync GEMM: D = F @ W^T ----------------
// CTA tile 128x128, KC=192 (3 x 64-k half-blocks), 2 stages, 24 iterations.
#define TM 128
#define TN 128
#define KC 192
#define NITER (KDIM / KC)             // 24
#define STAGES 2
#define GEMM_THREADS 256
#define KBLOCKS 3                     // 64-k blocks per K-chunk
#define HALF_TILE_BYTES (128 * 128)   // 128 rows x 64 k fp16 = 16 KB
#define TILE_BYTES  (KBLOCKS * HALF_TILE_BYTES)   // 48 KB per operand
#define STAGE_BYTES (2 * TILE_BYTES)               // A + B = 96 KB
#define SMEM_DYN_TOTAL (1024 + STAGES * STAGE_BYTES)   // ~193 KB

__device__ __forceinline__ void load_stage(uint32_t tiles_base, int it,
                                           int tid, int m0, int n0) {
    uint32_t abase = tiles_base + (uint32_t)(it % STAGES) * STAGE_BYTES;
    size_t k0 = (size_t)it * KC;
    const __half* Fs = F_buf + (size_t)m0 * KDIM + k0;
    const __half* Ws = W_buf + (size_t)n0 * KDIM + k0;
    // 6144 16B-chunks per stage: [A kb0|A kb1|A kb2|B kb0|B kb1|B kb2]
#pragma unroll
    for (int c = 0; c < 24; c++) {
        int chunk = tid + c * GEMM_THREADS;     // 0..6143
        int isB  = (chunk >= 3072);
        int sub  = isB ? (chunk - 3072) : chunk;
        int kb   = sub >> 10;                   // 0..2
        int row  = (sub >> 3) & 127;
        int q    = sub & 7;
        const __half* src = (isB ? Ws : Fs) + (size_t)row * KDIM + kb * 64 + q * 8;
        uint32_t dst = abase + (uint32_t)isB * TILE_BYTES
                     + (uint32_t)kb * HALF_TILE_BYTES
                     + SMEM_SWZ((uint32_t)(row * 128 + q * 16));
        asm volatile("cp.async.cg.shared.global [%0], [%1], 16;"
                     :: "r"(dst), "l"(src));
    }
    asm volatile("cp.async.commit_group;" ::: "memory");
}

__global__ void __launch_bounds__(GEMM_THREADS, 1)
kan_gemm_kernel(float* __restrict__ out) {
    extern __shared__ char smem[];
    uint32_t tiles_base = (smem_u32(smem) + 1023u) & ~1023u;

    int tid = threadIdx.x;
    int wid = tid >> 5;
    int lane = tid & 31;
    int m0 = (blockIdx.x >> 2) * TM;     // 32 M-tiles
    int n0 = (blockIdx.x & 3) * TN;      // 4 N-tiles

    // warp sub-tile: 2 (M) x 4 (N) warps, each 64x32
    int wm = (wid >> 2) * 64;
    int wn = (wid & 3) * 32;

    // ldmatrix lane mappings
    int a_row = lane & 15;
    int a_kh  = (lane >> 4) << 3;
    int b_nr  = (lane & 7) + ((lane >> 4) << 3);
    int b_kh  = ((lane >> 3) & 1) << 3;

    float acc[4][4][4];
#pragma unroll
    for (int i = 0; i < 4; i++)
#pragma unroll
        for (int j = 0; j < 4; j++)
#pragma unroll
            for (int t = 0; t < 4; t++) acc[i][j][t] = 0.0f;

    // preload stage 0
    load_stage(tiles_base, 0, tid, m0, n0);

    for (int it = 0; it < NITER; it++) {
        // stage `it` must be fully landed
        asm volatile("cp.async.wait_group 0;" ::: "memory");
        __syncthreads();

        if (it + 1 < NITER)
            load_stage(tiles_base, it + 1, tid, m0, n0);

        uint32_t Ab = tiles_base + (uint32_t)(it % STAGES) * STAGE_BYTES;
        uint32_t Bb = Ab + TILE_BYTES;

#pragma unroll
        for (int ks = 0; ks < 12; ks++) {
            uint32_t kboff = (uint32_t)(ks >> 2) * HALF_TILE_BYTES;
            int kk = (ks & 3) * 16;
            uint32_t a[4][4];
#pragma unroll
            for (int mi = 0; mi < 4; mi++) {
                uint32_t addr = Ab + kboff + SMEM_SWZ(
                    (uint32_t)((wm + mi * 16 + a_row) * 128 + (kk + a_kh) * 2));
                ldsm4(a[mi][0], a[mi][1], a[mi][2], a[mi][3], addr);
            }
            uint32_t b[8];
#pragma unroll
            for (int j = 0; j < 2; j++) {
                uint32_t addr = Bb + kboff + SMEM_SWZ(
                    (uint32_t)((wn + j * 16 + b_nr) * 128 + (kk + b_kh) * 2));
                ldsm4(b[j * 4 + 0], b[j * 4 + 1], b[j * 4 + 2], b[j * 4 + 3], addr);
            }
#pragma unroll
            for (int mi = 0; mi < 4; mi++)
#pragma unroll
                for (int nb = 0; nb < 4; nb++)
                    mma16816(acc[mi][nb], a[mi], b[nb * 2], b[nb * 2 + 1]);
        }
    }

    // epilogue: register accumulators -> gmem (float2 stores)
    int g = lane >> 2;
    int q = lane & 3;
#pragma unroll
    for (int mi = 0; mi < 4; mi++) {
#pragma unroll
        for (int nb = 0; nb < 4; nb++) {
            int row = m0 + wm + mi * 16 + g;
            int col = n0 + wn + nb * 8 + q * 2;
            float2 v0 = make_float2(acc[mi][nb][0], acc[mi][nb][1]);
            float2 v1 = make_float2(acc[mi][nb][2], acc[mi][nb][3]);
            *reinterpret_cast<float2*>(&out[(size_t)row * OUT_F + col]) = v0;
            *reinterpret_cast<float2*>(&out[(size_t)(row + 8) * OUT_F + col]) = v1;
        }
    }
}

// ---------------- launch ----------------
extern "C" void kernel_launch(void* const* d_in, const int* in_sizes, int n_in,
                              void* d_out, int out_size) {
    const float* x  = (const float*)d_in[0];   // (4096, 512)
    const float* sw = (const float*)d_in[1];   // (512, 512, 8)
    const float* ba = (const float*)d_in[2];   // (512, 512)
    const float* gp = (const float*)d_in[3];   // (8,)
    float* out = (float*)d_out;                // (4096, 512)

    prep_kernel<<<W_BLOCKS + F_BLOCKS, 256>>>(x, sw, ba, gp);

    cudaFuncSetAttribute(kan_gemm_kernel,
                         cudaFuncAttributeMaxDynamicSharedMemorySize,
                         SMEM_DYN_TOTAL);
    kan_gemm_kernel<<<(BATCH / TM) * (OUT_F / TN), GEMM_THREADS,
                      SMEM_DYN_TOTAL>>>(out);
}